// round 2
// baseline (speedup 1.0000x reference)
#include <cuda_runtime.h>
#include <cstdint>
#include <math.h>

#define BB 64
#define TT 512
#define DD 256
#define HH 256
#define KK (DD + HH)   // 512
#define PAD 68         // hx row pitch in floats (16B-aligned, conflict-mitigating)
#define NTHR 256
#define NBLK 128
#define DIRBLK 64      // blocks per direction
#define NBAR (TT + 1)  // barriers per launch per direction

// ---------------- device scratch (static allocation, allowed) ----------------
__device__ float g_xt[2][TT][DD][BB];     // pre-transposed inputs: [dir][t][k][b]  (64 MB)
__device__ float g_hb[2][2][HH][BB];      // double-buffered hidden: [dir][phase][n][b]
__device__ unsigned g_bcnt[2];            // per-direction barrier counters (zero-init)
__device__ unsigned g_bsns[2];            // per-direction barrier sense   (zero-init)

__device__ __forceinline__ float sigf(float v) { return 1.f / (1.f + expf(-v)); }

// Sense-reversal barrier across the 64 blocks of one direction.
// Self-resetting: after the last generation (gen = TT), sense wraps to 0 and
// count is 0, so repeated graph replays see pristine state.
__device__ __forceinline__ void dir_barrier(int dir, unsigned gen) {
    __threadfence();          // every thread's prior global writes -> device visible
    __syncthreads();
    if (threadIdx.x == 0) {
        unsigned arrived = atomicAdd(&g_bcnt[dir], 1u);
        if (arrived == DIRBLK - 1) {
            atomicExch(&g_bcnt[dir], 0u);
            __threadfence();
            atomicExch(&g_bsns[dir], (gen + 1u) % NBAR);
        } else {
            while (*((volatile unsigned*)&g_bsns[dir]) == gen) __nanosleep(64);
        }
        __threadfence();
    }
    __syncthreads();
}

extern "C" __global__ void __launch_bounds__(NTHR, 1)
bilstm_kernel(const float* __restrict__ x,
              const int*   __restrict__ lens,
              const float* __restrict__ Wih_f, const float* __restrict__ Whh_f,
              const float* __restrict__ bih_f, const float* __restrict__ bhh_f,
              const float* __restrict__ Wih_b, const float* __restrict__ Whh_b,
              const float* __restrict__ bih_b, const float* __restrict__ bhh_b,
              float* __restrict__ out)
{
    extern __shared__ float smem[];
    float* hx   = smem;                     // [KK][PAD]  staged [x_t ; h], k-major, b contiguous
    float* wt   = hx + KK * PAD;            // [KK][16]   transposed weight slice (16 rows)
    float* red  = wt + KK * 16;             // [16][3][64] k-split partial sums
    float* bsv  = red + 16 * 3 * 64;        // [16]       bih+bhh for this block's rows
    int*   slen = (int*)(bsv + 16);         // [64]

    const int tid = threadIdx.x;
    const int dir = blockIdx.x >> 6;        // 0 = forward, 1 = backward
    const int nb  = blockIdx.x & 63;        // hidden-dim chunk: n in [4*nb, 4*nb+4)

    const float* Wih = dir ? Wih_b : Wih_f;
    const float* Whh = dir ? Whh_b : Whh_f;
    const float* bih = dir ? bih_b : bih_f;
    const float* bhh = dir ? bhh_b : bhh_f;

    // ---------------- prologue ----------------
    for (int i = tid; i < BB; i += NTHR) slen[i] = lens[i];

    // Weight slice, transposed to [k][r16], r = nl*4 + gate (gate order i,f,g,o)
    for (int idx = tid; idx < KK * 16; idx += NTHR) {
        int k = idx >> 4, r = idx & 15;
        int nl = r >> 2, g = r & 3;
        int j = g * HH + nb * 4 + nl;                   // row in [4H, *] weight
        wt[idx] = (k < DD) ? Wih[(size_t)j * DD + k] : Whh[(size_t)j * HH + (k - DD)];
    }
    if (tid < 16) {
        int nl = tid >> 2, g = tid & 3;
        int j = g * HH + nb * 4 + nl;
        bsv[tid] = bih[j] + bhh[j];
    }
    // zero both h phases for this direction (split across the 64 dir-blocks)
    {
        float* hb = &g_hb[dir][0][0][0];
        const int total = 2 * HH * BB;
        for (int i = nb * NTHR + tid; i < total; i += DIRBLK * NTHR) hb[i] = 0.f;
    }
    __syncthreads();   // slen ready

    // Build pre-transposed x for this direction: xt[s][k][b].
    // Backward uses the reference's inversed index:
    //   t = T-1 - ((T - len[b] + s) % T)
    for (int s = nb; s < TT; s += DIRBLK) {
        float* dst = &g_xt[dir][s][0][0];
        const int k = tid;                 // 0..255 == DD
        for (int b0 = 0; b0 < BB; b0 += 4) {
            int t0, t1, t2, t3;
            if (dir == 0) { t0 = t1 = t2 = t3 = s; }
            else {
                t0 = TT - 1 - ((TT - slen[b0 + 0] + s) % TT);
                t1 = TT - 1 - ((TT - slen[b0 + 1] + s) % TT);
                t2 = TT - 1 - ((TT - slen[b0 + 2] + s) % TT);
                t3 = TT - 1 - ((TT - slen[b0 + 3] + s) % TT);
            }
            float4 v;
            v.x = x[((size_t)(b0 + 0) * TT + t0) * DD + k];
            v.y = x[((size_t)(b0 + 1) * TT + t1) * DD + k];
            v.z = x[((size_t)(b0 + 2) * TT + t2) * DD + k];
            v.w = x[((size_t)(b0 + 3) * TT + t3) * DD + k];
            *(float4*)&dst[k * BB + b0] = v;
        }
    }

    dir_barrier(dir, 0u);

    // ---------------- recurrence ----------------
    // Thread decomposition: kq = K-quarter (0..3), bg = batch group (4 batches),
    // nl = local hidden dim (0..3). Thread tile = 4 gates x 4 batches.
    const int kq = tid >> 6;
    const int r  = tid & 63;
    const int bg = r & 15;
    const int nl = r >> 4;
    const int n  = nb * 4 + nl;

    float creg0 = 0.f, creg1 = 0.f, creg2 = 0.f, creg3 = 0.f;  // cell state (kq==0 threads)
    int p = 0;

    for (int s = 0; s < TT; ++s) {
        // stage [x_s ; h_p] into smem, k-major with batch contiguous
        const float4* xs = (const float4*)&g_xt[dir][s][0][0];  // 256*16 float4
        const float4* hs = (const float4*)&g_hb[dir][p][0][0];  // 256*16 float4
        #pragma unroll 4
        for (int i = tid; i < KK * 16; i += NTHR) {
            int k = i >> 4, c = i & 15;
            float4 v = (k < DD) ? xs[i] : hs[i - DD * 16];
            *(float4*)&hx[k * PAD + c * 4] = v;
        }
        __syncthreads();

        float acc[16];
        #pragma unroll
        for (int i = 0; i < 16; ++i) acc[i] = 0.f;

        const float* hxp = hx + (kq * 128) * PAD + bg * 4;
        const float* wtp = wt + (kq * 128) * 16 + nl * 4;
        #pragma unroll 8
        for (int kk = 0; kk < 128; ++kk) {
            float4 h4 = *(const float4*)(hxp + kk * PAD);   // 4 batches at this k
            float4 w4 = *(const float4*)(wtp + kk * 16);    // 4 gates   at this k
            acc[0]  += w4.x * h4.x; acc[1]  += w4.x * h4.y; acc[2]  += w4.x * h4.z; acc[3]  += w4.x * h4.w;
            acc[4]  += w4.y * h4.x; acc[5]  += w4.y * h4.y; acc[6]  += w4.y * h4.z; acc[7]  += w4.y * h4.w;
            acc[8]  += w4.z * h4.x; acc[9]  += w4.z * h4.y; acc[10] += w4.z * h4.z; acc[11] += w4.z * h4.w;
            acc[12] += w4.w * h4.x; acc[13] += w4.w * h4.y; acc[14] += w4.w * h4.z; acc[15] += w4.w * h4.w;
        }

        // reduce the 4 K-quarters: kq!=0 publish, kq==0 accumulate
        if (kq) {
            #pragma unroll
            for (int i = 0; i < 16; ++i)
                red[i * 192 + (kq - 1) * 64 + r] = acc[i];
        }
        __syncthreads();

        if (kq == 0) {
            #pragma unroll
            for (int i = 0; i < 16; ++i)
                acc[i] += red[i * 192 + r] + red[i * 192 + 64 + r] + red[i * 192 + 128 + r];

            const float b0v = bsv[nl * 4 + 0];
            const float b1v = bsv[nl * 4 + 1];
            const float b2v = bsv[nl * 4 + 2];
            const float b3v = bsv[nl * 4 + 3];

            float4 hv;
            float* hvp = &hv.x;
            #pragma unroll
            for (int bi = 0; bi < 4; ++bi) {
                float pi = acc[0  + bi] + b0v;
                float pf = acc[4  + bi] + b1v;
                float pg = acc[8  + bi] + b2v;
                float po = acc[12 + bi] + b3v;
                float cprev = (bi == 0) ? creg0 : (bi == 1) ? creg1 : (bi == 2) ? creg2 : creg3;
                float cnew  = sigf(pf) * cprev + sigf(pi) * tanhf(pg);
                float hval  = sigf(po) * tanhf(cnew);
                if      (bi == 0) creg0 = cnew;
                else if (bi == 1) creg1 = cnew;
                else if (bi == 2) creg2 = cnew;
                else              creg3 = cnew;
                hvp[bi] = hval;

                const int b = bg * 4 + bi;
                const int L = slen[b];
                if (s < L) {
                    const int t = dir ? (L - 1 - s) : s;   // bwd states land re-reversed
                    out[((size_t)b * TT + t) * (2 * HH) + dir * HH + n] = hval;
                }
            }
            *(float4*)&g_hb[dir][p ^ 1][n][bg * 4] = hv;
        }

        dir_barrier(dir, (unsigned)(s + 1));
        p ^= 1;
    }
}

extern "C" void kernel_launch(void* const* d_in, const int* in_sizes, int n_in,
                              void* d_out, int out_size) {
    const float* x     = (const float*)d_in[0];
    const int*   lens  = (const int*)  d_in[1];
    const float* Wih_f = (const float*)d_in[2];
    const float* Whh_f = (const float*)d_in[3];
    const float* bih_f = (const float*)d_in[4];
    const float* bhh_f = (const float*)d_in[5];
    const float* Wih_b = (const float*)d_in[6];
    const float* Whh_b = (const float*)d_in[7];
    const float* bih_b = (const float*)d_in[8];
    const float* bhh_b = (const float*)d_in[9];
    float* out = (float*)d_out;

    // zero the padded/masked region (output beyond input_length must be 0)
    cudaMemsetAsync(out, 0, (size_t)out_size * sizeof(float), 0);

    const size_t smem_bytes =
        (size_t)(KK * PAD + KK * 16 + 16 * 3 * 64 + 16) * sizeof(float) + BB * sizeof(int);
    cudaFuncSetAttribute(bilstm_kernel,
                         cudaFuncAttributeMaxDynamicSharedMemorySize, (int)smem_bytes);

    bilstm_kernel<<<NBLK, NTHR, smem_bytes>>>(x, lens, Wih_f, Whh_f, bih_f, bhh_f,
                                              Wih_b, Whh_b, bih_b, bhh_b, out);
}

// round 3
// speedup vs baseline: 1.0346x; 1.0346x over previous
#include <cuda_runtime.h>
#include <cstdint>
#include <math.h>

#define BB 64
#define TT 512
#define DD 256
#define HH 256
#define KK (DD + HH)   // 512
#define PAD 68         // hx row pitch in floats (16B-aligned, conflict-mitigating)
#define NTHR 256
#define NBLK 128
#define DIRBLK 64      // blocks per direction
#define NBAR (TT + 1)  // barriers per launch per direction

// ---------------- device scratch (static allocation, allowed) ----------------
__device__ float g_xt[2][TT][DD][BB];     // pre-transposed inputs: [dir][t][k][b]  (64 MB)
__device__ float g_hb[2][2][HH][BB];      // double-buffered hidden: [dir][phase][n][b]
__device__ unsigned g_bcnt[2];            // per-direction barrier counters (zero-init)
__device__ unsigned g_bsns[2];            // per-direction barrier sense   (zero-init)

__device__ __forceinline__ float sigf(float v) { return 1.f / (1.f + expf(-v)); }

// Sense-reversal barrier across the 64 blocks of one direction.
// Self-resetting: after the last generation (gen = TT), sense wraps to 0 and
// count is 0, so repeated graph replays see pristine state.
__device__ __forceinline__ void dir_barrier(int dir, unsigned gen) {
    __threadfence();          // every thread's prior global writes -> device visible
    __syncthreads();
    if (threadIdx.x == 0) {
        unsigned arrived = atomicAdd(&g_bcnt[dir], 1u);
        if (arrived == DIRBLK - 1) {
            atomicExch(&g_bcnt[dir], 0u);
            __threadfence();
            atomicExch(&g_bsns[dir], (gen + 1u) % NBAR);
        } else {
            while (*((volatile unsigned*)&g_bsns[dir]) == gen) __nanosleep(64);
        }
        __threadfence();
    }
    __syncthreads();
}

extern "C" __global__ void __launch_bounds__(NTHR, 1)
bilstm_kernel(const float* __restrict__ x,
              const int*   __restrict__ lens,
              const float* __restrict__ Wih_f, const float* __restrict__ Whh_f,
              const float* __restrict__ bih_f, const float* __restrict__ bhh_f,
              const float* __restrict__ Wih_b, const float* __restrict__ Whh_b,
              const float* __restrict__ bih_b, const float* __restrict__ bhh_b,
              float* __restrict__ out)
{
    extern __shared__ float smem[];
    float* hx   = smem;                     // [KK][PAD]  staged [x_t ; h], k-major, b contiguous
    float* wt   = hx + KK * PAD;            // [KK][16]   transposed weight slice (16 rows)
    float* red  = wt + KK * 16;             // [16][3][64] k-split partial sums
    float* bsv  = red + 16 * 3 * 64;        // [16]       bih+bhh for this block's rows
    int*   slen = (int*)(bsv + 16);         // [64]

    const int tid = threadIdx.x;
    const int dir = blockIdx.x >> 6;        // 0 = forward, 1 = backward
    const int nb  = blockIdx.x & 63;        // hidden-dim chunk: n in [4*nb, 4*nb+4)

    const float* Wih = dir ? Wih_b : Wih_f;
    const float* Whh = dir ? Whh_b : Whh_f;
    const float* bih = dir ? bih_b : bih_f;
    const float* bhh = dir ? bhh_b : bhh_f;

    // ---------------- prologue ----------------
    for (int i = tid; i < BB; i += NTHR) slen[i] = lens[i];

    // Weight slice, transposed to [k][r16], r = nl*4 + gate (gate order i,f,g,o)
    for (int idx = tid; idx < KK * 16; idx += NTHR) {
        int k = idx >> 4, r = idx & 15;
        int nl = r >> 2, g = r & 3;
        int j = g * HH + nb * 4 + nl;                   // row in [4H, *] weight
        wt[idx] = (k < DD) ? Wih[(size_t)j * DD + k] : Whh[(size_t)j * HH + (k - DD)];
    }
    if (tid < 16) {
        int nl = tid >> 2, g = tid & 3;
        int j = g * HH + nb * 4 + nl;
        bsv[tid] = bih[j] + bhh[j];
    }
    // zero both h phases for this direction (split across the 64 dir-blocks)
    {
        float* hb = &g_hb[dir][0][0][0];
        const int total = 2 * HH * BB;
        for (int i = nb * NTHR + tid; i < total; i += DIRBLK * NTHR) hb[i] = 0.f;
    }
    __syncthreads();   // slen ready

    // Build pre-transposed x for this direction: xt[s][k][b].
    // Backward uses the reference's inversed index:
    //   t = T-1 - ((T - len[b] + s) % T)
    for (int s = nb; s < TT; s += DIRBLK) {
        float* dst = &g_xt[dir][s][0][0];
        const int k = tid;                 // 0..255 == DD
        for (int b0 = 0; b0 < BB; b0 += 4) {
            int t0, t1, t2, t3;
            if (dir == 0) { t0 = t1 = t2 = t3 = s; }
            else {
                t0 = TT - 1 - ((TT - slen[b0 + 0] + s) % TT);
                t1 = TT - 1 - ((TT - slen[b0 + 1] + s) % TT);
                t2 = TT - 1 - ((TT - slen[b0 + 2] + s) % TT);
                t3 = TT - 1 - ((TT - slen[b0 + 3] + s) % TT);
            }
            float4 v;
            v.x = x[((size_t)(b0 + 0) * TT + t0) * DD + k];
            v.y = x[((size_t)(b0 + 1) * TT + t1) * DD + k];
            v.z = x[((size_t)(b0 + 2) * TT + t2) * DD + k];
            v.w = x[((size_t)(b0 + 3) * TT + t3) * DD + k];
            *(float4*)&dst[k * BB + b0] = v;
        }
    }

    dir_barrier(dir, 0u);

    // ---------------- recurrence ----------------
    // Thread decomposition: kq = K-quarter (0..3), bg = batch group (4 batches),
    // nl = local hidden dim (0..3). Thread tile = 4 gates x 4 batches.
    const int kq = tid >> 6;
    const int r  = tid & 63;
    const int bg = r & 15;
    const int nl = r >> 4;
    const int n  = nb * 4 + nl;

    float creg0 = 0.f, creg1 = 0.f, creg2 = 0.f, creg3 = 0.f;  // cell state (kq==0 threads)
    int p = 0;

    for (int s = 0; s < TT; ++s) {
        // stage [x_s ; h_p] into smem, k-major with batch contiguous
        const float4* xs = (const float4*)&g_xt[dir][s][0][0];  // 256*16 float4
        const float4* hs = (const float4*)&g_hb[dir][p][0][0];  // 256*16 float4
        #pragma unroll 4
        for (int i = tid; i < KK * 16; i += NTHR) {
            int k = i >> 4, c = i & 15;
            float4 v = (k < DD) ? xs[i] : hs[i - DD * 16];
            *(float4*)&hx[k * PAD + c * 4] = v;
        }
        __syncthreads();

        float acc[16];
        #pragma unroll
        for (int i = 0; i < 16; ++i) acc[i] = 0.f;

        const float* hxp = hx + (kq * 128) * PAD + bg * 4;
        const float* wtp = wt + (kq * 128) * 16 + nl * 4;
        #pragma unroll 8
        for (int kk = 0; kk < 128; ++kk) {
            float4 h4 = *(const float4*)(hxp + kk * PAD);   // 4 batches at this k
            float4 w4 = *(const float4*)(wtp + kk * 16);    // 4 gates   at this k
            acc[0]  += w4.x * h4.x; acc[1]  += w4.x * h4.y; acc[2]  += w4.x * h4.z; acc[3]  += w4.x * h4.w;
            acc[4]  += w4.y * h4.x; acc[5]  += w4.y * h4.y; acc[6]  += w4.y * h4.z; acc[7]  += w4.y * h4.w;
            acc[8]  += w4.z * h4.x; acc[9]  += w4.z * h4.y; acc[10] += w4.z * h4.z; acc[11] += w4.z * h4.w;
            acc[12] += w4.w * h4.x; acc[13] += w4.w * h4.y; acc[14] += w4.w * h4.z; acc[15] += w4.w * h4.w;
        }

        // reduce the 4 K-quarters: kq!=0 publish, kq==0 accumulate
        if (kq) {
            #pragma unroll
            for (int i = 0; i < 16; ++i)
                red[i * 192 + (kq - 1) * 64 + r] = acc[i];
        }
        __syncthreads();

        if (kq == 0) {
            #pragma unroll
            for (int i = 0; i < 16; ++i)
                acc[i] += red[i * 192 + r] + red[i * 192 + 64 + r] + red[i * 192 + 128 + r];

            const float b0v = bsv[nl * 4 + 0];
            const float b1v = bsv[nl * 4 + 1];
            const float b2v = bsv[nl * 4 + 2];
            const float b3v = bsv[nl * 4 + 3];

            float4 hv;
            float* hvp = &hv.x;
            #pragma unroll
            for (int bi = 0; bi < 4; ++bi) {
                float pi = acc[0  + bi] + b0v;
                float pf = acc[4  + bi] + b1v;
                float pg = acc[8  + bi] + b2v;
                float po = acc[12 + bi] + b3v;
                float cprev = (bi == 0) ? creg0 : (bi == 1) ? creg1 : (bi == 2) ? creg2 : creg3;
                float cnew  = sigf(pf) * cprev + sigf(pi) * tanhf(pg);
                float hval  = sigf(po) * tanhf(cnew);
                if      (bi == 0) creg0 = cnew;
                else if (bi == 1) creg1 = cnew;
                else if (bi == 2) creg2 = cnew;
                else              creg3 = cnew;
                hvp[bi] = hval;

                const int b = bg * 4 + bi;
                const int L = slen[b];
                if (s < L) {
                    const int t = dir ? (L - 1 - s) : s;   // bwd states land re-reversed
                    out[((size_t)b * TT + t) * (2 * HH) + dir * HH + n] = hval;
                }
            }
            *(float4*)&g_hb[dir][p ^ 1][n][bg * 4] = hv;
        }

        dir_barrier(dir, (unsigned)(s + 1));
        p ^= 1;
    }
}

extern "C" void kernel_launch(void* const* d_in, const int* in_sizes, int n_in,
                              void* d_out, int out_size) {
    const float* x     = (const float*)d_in[0];
    const int*   lens  = (const int*)  d_in[1];
    const float* Wih_f = (const float*)d_in[2];
    const float* Whh_f = (const float*)d_in[3];
    const float* bih_f = (const float*)d_in[4];
    const float* bhh_f = (const float*)d_in[5];
    const float* Wih_b = (const float*)d_in[6];
    const float* Whh_b = (const float*)d_in[7];
    const float* bih_b = (const float*)d_in[8];
    const float* bhh_b = (const float*)d_in[9];
    float* out = (float*)d_out;

    // zero the padded/masked region (output beyond input_length must be 0)
    cudaMemsetAsync(out, 0, (size_t)out_size * sizeof(float), 0);

    const size_t smem_bytes =
        (size_t)(KK * PAD + KK * 16 + 16 * 3 * 64 + 16) * sizeof(float) + BB * sizeof(int);
    cudaFuncSetAttribute(bilstm_kernel,
                         cudaFuncAttributeMaxDynamicSharedMemorySize, (int)smem_bytes);

    bilstm_kernel<<<NBLK, NTHR, smem_bytes>>>(x, lens, Wih_f, Whh_f, bih_f, bhh_f,
                                              Wih_b, Whh_b, bih_b, bhh_b, out);
}